// round 3
// baseline (speedup 1.0000x reference)
#include <cuda_runtime.h>

#define NMAX 100000
#define HIDD 64
#define FIN  128

// Scratch (allocation-free rule: __device__ globals)
__device__ float g_deg[NMAX];            // degree -> rsqrt(degree)
__device__ float g_hl[NMAX * HIDD];      // linear (pre-aggregation) features
__device__ float g_h [NMAX * HIDD];      // aggregated features (h1, then h2)
__device__ float g_ab[NMAX * 2 * HIDD];  // [A | B] per node for edge MLP
__device__ float g_wab[HIDD * 2 * HIDD]; // repacked lin1_W: [64][128]

__global__ void deg_init(float* __restrict__ deg, int n) {
    int i = blockIdx.x * blockDim.x + threadIdx.x;
    if (i < n) deg[i] = 1.0f;  // self-loop
}

__global__ void deg_count(const int* __restrict__ col, float* __restrict__ deg, int E) {
    int e = blockIdx.x * blockDim.x + threadIdx.x;
    if (e < E) atomicAdd(&deg[col[e]], 1.0f);
}

__global__ void deg_rsqrt(float* __restrict__ deg, int n) {
    int i = blockIdx.x * blockDim.x + threadIdx.x;
    if (i < n) deg[i] = rsqrtf(deg[i]);
}

// Y[nrows,N] = X[nrows,K] @ W[K,N], W + X tile staged in smem, K fully unrolled.
template <int K, int N>
__global__ void gemm_rm(const float* __restrict__ X, const float* __restrict__ W,
                        float* __restrict__ Y, int nrows) {
    constexpr int CG = N / 4;       // float4 column groups
    constexpr int R  = 256 / CG;    // rows per block
    __shared__ float Ws[K][N];
    __shared__ float Xs[R][K];
    int tid = threadIdx.x;
    for (int i = tid; i < K * N; i += 256) Ws[i / N][i % N] = W[i];
    int row0 = blockIdx.x * R;
    for (int i = tid; i < R * K; i += 256) {
        int rr = i / K, kk = i - rr * K;
        int gr = row0 + rr;
        Xs[rr][kk] = (gr < nrows) ? X[(size_t)gr * K + kk] : 0.0f;
    }
    __syncthreads();
    int cg = tid % CG, ry = tid / CG;
    float a0 = 0.f, a1 = 0.f, a2 = 0.f, a3 = 0.f;
#pragma unroll
    for (int k = 0; k < K; k++) {
        float xv = Xs[ry][k];
        float4 w = *reinterpret_cast<const float4*>(&Ws[k][cg * 4]);
        a0 += xv * w.x; a1 += xv * w.y; a2 += xv * w.z; a3 += xv * w.w;
    }
    int gr = row0 + ry;
    if (gr < nrows) {
        float4 o = make_float4(a0, a1, a2, a3);
        *reinterpret_cast<float4*>(&Y[(size_t)gr * N + cg * 4]) = o;
    }
}

// h[v] = hl[v] * dinv[v]^2   (self-loop contribution, initializes accumulator)
__global__ void selfloop_init(const float* __restrict__ hl, const float* __restrict__ dinv,
                              float* __restrict__ h, int n) {
    int i = blockIdx.x * blockDim.x + threadIdx.x;  // float4 index, 16 per row
    if (i < n * 16) {
        int v = i >> 4;
        float d = dinv[v];
        float s = d * d;
        float4 x = reinterpret_cast<const float4*>(hl)[i];
        x.x *= s; x.y *= s; x.z *= s; x.w *= s;
        reinterpret_cast<float4*>(h)[i] = x;
    }
}

// h[col[e]] += hl[row[e]] * dinv[row]*dinv[col]; 16 threads per edge (float4 each)
__global__ void scatter_edges(const int* __restrict__ row, const int* __restrict__ col,
                              const float* __restrict__ dinv, const float* __restrict__ hl,
                              float* __restrict__ h, int E) {
    int gid = blockIdx.x * blockDim.x + threadIdx.x;
    int e = gid >> 4;
    if (e >= E) return;
    int l = gid & 15;
    int r = row[e], c = col[e];
    float nrm = dinv[r] * dinv[c];
    float4 v = *reinterpret_cast<const float4*>(&hl[(size_t)r * 64 + l * 4]);
    float* p = &h[(size_t)c * 64 + l * 4];
    atomicAdd(p + 0, v.x * nrm);
    atomicAdd(p + 1, v.y * nrm);
    atomicAdd(p + 2, v.z * nrm);
    atomicAdd(p + 3, v.w * nrm);
}

__global__ void bias_relu(float* __restrict__ h, const float* __restrict__ b, int n) {
    __shared__ float sb[64];
    if (threadIdx.x < 64) sb[threadIdx.x] = b[threadIdx.x];
    __syncthreads();
    int i = blockIdx.x * blockDim.x + threadIdx.x;
    if (i < n * 16) {
        int j = (i & 15) * 4;
        float4 x = reinterpret_cast<float4*>(h)[i];
        x.x = fmaxf(x.x + sb[j + 0], 0.f);
        x.y = fmaxf(x.y + sb[j + 1], 0.f);
        x.z = fmaxf(x.z + sb[j + 2], 0.f);
        x.w = fmaxf(x.w + sb[j + 3], 0.f);
        reinterpret_cast<float4*>(h)[i] = x;
    }
}

// wab[k][0:64]  = lin1_W[k][:]       (rows 0..63  -> A path)
// wab[k][64:128]= lin1_W[64+k][:]    (rows 64..127-> B path)
__global__ void repack_wab(const float* __restrict__ l1W, float* __restrict__ wab) {
    int i = blockIdx.x * blockDim.x + threadIdx.x;
    if (i < 64 * 128) {
        int k = i >> 7, nn = i & 127;
        wab[i] = (nn < 64) ? l1W[k * 64 + nn] : l1W[(64 + k) * 64 + (nn - 64)];
    }
}

// per edge: z = relu(A[r]+B[c]+b1); logits = z@L2 + b2; log_softmax(2)
__global__ void edge_mlp(const int* __restrict__ row, const int* __restrict__ col,
                         const float* __restrict__ ab, const float* __restrict__ l1b,
                         const float* __restrict__ l2w, const float* __restrict__ l2b,
                         float* __restrict__ out, int E) {
    __shared__ float s1b[64], s2w[128], s2b[2];
    int tid = threadIdx.x;
    if (tid < 64)        s1b[tid]       = l1b[tid];
    else if (tid < 192)  s2w[tid - 64]  = l2w[tid - 64];
    else if (tid < 194)  s2b[tid - 192] = l2b[tid - 192];
    __syncthreads();
    int gid = blockIdx.x * 256 + tid;
    int e = gid >> 4;
    if (e >= E) return;
    int l = gid & 15;
    int r = row[e], c = col[e];
    float4 a = *reinterpret_cast<const float4*>(&ab[(size_t)r * 128 + l * 4]);
    float4 b = *reinterpret_cast<const float4*>(&ab[(size_t)c * 128 + 64 + l * 4]);
    int j = l * 4;
    float s0 = 0.f, s1 = 0.f, z;
    z = fmaxf(a.x + b.x + s1b[j + 0], 0.f); s0 += z * s2w[(j + 0) * 2]; s1 += z * s2w[(j + 0) * 2 + 1];
    z = fmaxf(a.y + b.y + s1b[j + 1], 0.f); s0 += z * s2w[(j + 1) * 2]; s1 += z * s2w[(j + 1) * 2 + 1];
    z = fmaxf(a.z + b.z + s1b[j + 2], 0.f); s0 += z * s2w[(j + 2) * 2]; s1 += z * s2w[(j + 2) * 2 + 1];
    z = fmaxf(a.w + b.w + s1b[j + 3], 0.f); s0 += z * s2w[(j + 3) * 2]; s1 += z * s2w[(j + 3) * 2 + 1];
#pragma unroll
    for (int off = 8; off > 0; off >>= 1) {
        s0 += __shfl_down_sync(0xFFFFFFFFu, s0, off, 16);
        s1 += __shfl_down_sync(0xFFFFFFFFu, s1, off, 16);
    }
    if (l == 0) {
        s0 += s2b[0]; s1 += s2b[1];
        float m = fmaxf(s0, s1);
        float lse = m + logf(expf(s0 - m) + expf(s1 - m));
        float2 o = make_float2(s0 - lse, s1 - lse);
        *reinterpret_cast<float2*>(&out[2 * (size_t)e]) = o;
    }
}

extern "C" void kernel_launch(void* const* d_in, const int* in_sizes, int n_in,
                              void* d_out, int out_size) {
    const float* x   = (const float*)d_in[0];
    const int*   ei  = (const int*)d_in[1];     // edge_index is int32 (JAX x64 disabled)
    const float* W1  = (const float*)d_in[2];
    const float* b1  = (const float*)d_in[3];
    const float* W2  = (const float*)d_in[4];
    const float* b2  = (const float*)d_in[5];
    const float* l1W = (const float*)d_in[6];
    const float* l1b = (const float*)d_in[7];
    const float* l2W = (const float*)d_in[8];
    const float* l2b = (const float*)d_in[9];
    float* out = (float*)d_out;

    int n = in_sizes[0] / FIN;
    int E = in_sizes[1] / 2;
    const int* row = ei;
    const int* col = ei + E;

    float *deg, *hl, *h, *ab, *wab;
    cudaGetSymbolAddress((void**)&deg, g_deg);
    cudaGetSymbolAddress((void**)&hl,  g_hl);
    cudaGetSymbolAddress((void**)&h,   g_h);
    cudaGetSymbolAddress((void**)&ab,  g_ab);
    cudaGetSymbolAddress((void**)&wab, g_wab);

    const int T = 256;
    // degrees -> dinv
    deg_init <<<(n + T - 1) / T, T>>>(deg, n);
    deg_count<<<(E + T - 1) / T, T>>>(col, deg, E);
    deg_rsqrt<<<(n + T - 1) / T, T>>>(deg, n);

    // GCN layer 1
    gemm_rm<128, 64><<<(n + 15) / 16, 256>>>(x, W1, hl, n);
    selfloop_init<<<(n * 16 + T - 1) / T, T>>>(hl, deg, h, n);
    scatter_edges<<<(E * 16 + T - 1) / T, T>>>(row, col, deg, hl, h, E);
    bias_relu<<<(n * 16 + T - 1) / T, T>>>(h, b1, n);

    // GCN layer 2
    gemm_rm<64, 64><<<(n + 15) / 16, 256>>>(h, W2, hl, n);
    selfloop_init<<<(n * 16 + T - 1) / T, T>>>(hl, deg, h, n);
    scatter_edges<<<(E * 16 + T - 1) / T, T>>>(row, col, deg, hl, h, E);
    bias_relu<<<(n * 16 + T - 1) / T, T>>>(h, b2, n);

    // Edge MLP: precompute per-node A|B, then per-edge combine + log_softmax
    repack_wab<<<(64 * 128 + T - 1) / T, T>>>(l1W, wab);
    gemm_rm<64, 128><<<(n + 7) / 8, 256>>>(h, wab, ab, n);
    edge_mlp<<<(E * 16 + T - 1) / T, T>>>(row, col, ab, l1b, l2W, l2b, out, E);
}

// round 4
// speedup vs baseline: 2.4086x; 2.4086x over previous
#include <cuda_runtime.h>

#define NMAX 100000
#define EMAX 1600000
#define HIDD 64
#define FIN  128

// Scratch (allocation-free rule: __device__ globals)
__device__ int   g_cnt[NMAX];
__device__ int   g_off[NMAX + 1];
__device__ int   g_cur[NMAX];
__device__ int   g_esrc[EMAX];
__device__ int   g_bsum[512];
__device__ float g_dinv[NMAX];
__device__ float g_hl[NMAX * HIDD];      // dinv-scaled linear features
__device__ float g_h [NMAX * HIDD];      // aggregated features
__device__ float g_ab[NMAX * 2 * HIDD];  // [A | B] per node for edge MLP
__device__ float g_wab[HIDD * 2 * HIDD]; // repacked lin1_W: [64][128]

// ---------------- CSC build ----------------
__global__ void zero_cnt(int* __restrict__ cnt, int n) {
    int i = blockIdx.x * blockDim.x + threadIdx.x;
    if (i < n) cnt[i] = 0;
}

__global__ void count_in(const int* __restrict__ col, int* __restrict__ cnt, int E) {
    int e = blockIdx.x * blockDim.x + threadIdx.x;
    if (e < E) atomicAdd(&cnt[col[e]], 1);
}

__global__ void make_dinv(const int* __restrict__ cnt, float* __restrict__ dinv, int n) {
    int i = blockIdx.x * blockDim.x + threadIdx.x;
    if (i < n) dinv[i] = rsqrtf((float)cnt[i] + 1.0f);  // +1 self-loop
}

// block-wise exclusive scan (256/block), block totals to bsum
__global__ void scan1(const int* __restrict__ cnt, int* __restrict__ off,
                      int* __restrict__ bsum, int n) {
    __shared__ int s[256];
    int tid = threadIdx.x;
    int i = blockIdx.x * 256 + tid;
    int v = (i < n) ? cnt[i] : 0;
    s[tid] = v;
    __syncthreads();
#pragma unroll
    for (int d = 1; d < 256; d <<= 1) {
        int t = (tid >= d) ? s[tid - d] : 0;
        __syncthreads();
        s[tid] += t;
        __syncthreads();
    }
    if (i < n) off[i] = s[tid] - v;
    if (tid == 255) bsum[blockIdx.x] = s[255];
}

// exclusive scan of block sums (single block, nb <= 512)
__global__ void scan2(int* __restrict__ bsum, int nb) {
    __shared__ int s[512];
    int tid = threadIdx.x;
    int v = (tid < nb) ? bsum[tid] : 0;
    s[tid] = v;
    __syncthreads();
#pragma unroll
    for (int d = 1; d < 512; d <<= 1) {
        int t = (tid >= d) ? s[tid - d] : 0;
        __syncthreads();
        s[tid] += t;
        __syncthreads();
    }
    if (tid < nb) bsum[tid] = s[tid] - v;
}

__global__ void scan3(int* __restrict__ off, const int* __restrict__ bsum,
                      int* __restrict__ cur, int n, int E) {
    int i = blockIdx.x * 256 + threadIdx.x;
    if (i < n) {
        int o = off[i] + bsum[blockIdx.x];
        off[i] = o;
        cur[i] = o;
    }
    if (i == 0) off[n] = E;
}

__global__ void fill_csr(const int* __restrict__ row, const int* __restrict__ col,
                         int* __restrict__ cur, int* __restrict__ esrc, int E) {
    int e = blockIdx.x * blockDim.x + threadIdx.x;
    if (e < E) {
        int p = atomicAdd(&cur[col[e]], 1);
        esrc[p] = row[e];
    }
}

// ---------------- GEMM: Y[r,:] = (X[r,:] @ W) * (dinv ? dinv[r] : 1) ----------------
// 256 threads; per thread: 4 rows x 4 cols; K chunked at 64.
template <int K, int N>
__global__ void gemm_tiled(const float* __restrict__ X, const float* __restrict__ W,
                           const float* __restrict__ dinv, float* __restrict__ Y, int nrows) {
    constexpr int CG = N / 4;          // float4 column groups (16 or 32)
    constexpr int TR = 4;              // rows per thread
    constexpr int RQ = 256 / CG;       // row-quads per block
    constexpr int ROWS = RQ * TR;      // rows per block (64 or 32)
    constexpr int KC = 64;             // K chunk
    constexpr int NCH = K / KC;
    constexpr int XP = KC + 4;         // pad: 272B rows, 16B-aligned, bank-skewed
    __shared__ float Xs[ROWS][XP];
    __shared__ float Ws[KC][N];
    int tid = threadIdx.x;
    int row0 = blockIdx.x * ROWS;
    int cg = tid % CG, rq = tid / CG;
    float acc[TR][4] = {};

    for (int ch = 0; ch < NCH; ch++) {
        int k0 = ch * KC;
        for (int j = tid; j < ROWS * (KC / 4); j += 256) {
            int r = j / (KC / 4), kq = j % (KC / 4);
            int gr = row0 + r;
            float4 v = (gr < nrows)
                ? *reinterpret_cast<const float4*>(&X[(size_t)gr * K + k0 + kq * 4])
                : make_float4(0.f, 0.f, 0.f, 0.f);
            *reinterpret_cast<float4*>(&Xs[r][kq * 4]) = v;
        }
        for (int j = tid; j < KC * (N / 4); j += 256) {
            int k = j / (N / 4), nq = j % (N / 4);
            *reinterpret_cast<float4*>(&Ws[k][nq * 4]) =
                *reinterpret_cast<const float4*>(&W[(size_t)(k0 + k) * N + nq * 4]);
        }
        __syncthreads();
#pragma unroll
        for (int k = 0; k < KC; k++) {
            float4 w = *reinterpret_cast<const float4*>(&Ws[k][cg * 4]);
#pragma unroll
            for (int i = 0; i < TR; i++) {
                float xv = Xs[rq * TR + i][k];
                acc[i][0] += xv * w.x;
                acc[i][1] += xv * w.y;
                acc[i][2] += xv * w.z;
                acc[i][3] += xv * w.w;
            }
        }
        __syncthreads();
    }
#pragma unroll
    for (int i = 0; i < TR; i++) {
        int gr = row0 + rq * TR + i;
        if (gr < nrows) {
            float s = dinv ? dinv[gr] : 1.0f;
            float4 o = make_float4(acc[i][0] * s, acc[i][1] * s, acc[i][2] * s, acc[i][3] * s);
            *reinterpret_cast<float4*>(&Y[(size_t)gr * N + cg * 4]) = o;
        }
    }
}

// ---------------- aggregation: h[c] = relu(dinv[c]*(hls[c] + sum_in hls[src]) + b) ----------------
__global__ void gather_agg(const int* __restrict__ off, const int* __restrict__ esrc,
                           const float* __restrict__ hls, const float* __restrict__ dinv,
                           const float* __restrict__ bias, float* __restrict__ h, int n) {
    __shared__ float sb[64];
    if (threadIdx.x < 64) sb[threadIdx.x] = bias[threadIdx.x];
    __syncthreads();
    int gid = blockIdx.x * 256 + threadIdx.x;
    int c = gid >> 4;
    if (c >= n) return;
    int l = gid & 15;
    const float4* hp = reinterpret_cast<const float4*>(hls);
    float4 acc = hp[(size_t)c * 16 + l];  // self-loop term
    int s = off[c], e2 = off[c + 1];
    int j = s;
    for (; j + 1 < e2; j += 2) {
        int r0 = esrc[j], r1 = esrc[j + 1];
        float4 v0 = hp[(size_t)r0 * 16 + l];
        float4 v1 = hp[(size_t)r1 * 16 + l];
        acc.x += v0.x + v1.x; acc.y += v0.y + v1.y;
        acc.z += v0.z + v1.z; acc.w += v0.w + v1.w;
    }
    if (j < e2) {
        int r = esrc[j];
        float4 v = hp[(size_t)r * 16 + l];
        acc.x += v.x; acc.y += v.y; acc.z += v.z; acc.w += v.w;
    }
    float dc = dinv[c];
    int jb = l * 4;
    float4 o;
    o.x = fmaxf(acc.x * dc + sb[jb + 0], 0.f);
    o.y = fmaxf(acc.y * dc + sb[jb + 1], 0.f);
    o.z = fmaxf(acc.z * dc + sb[jb + 2], 0.f);
    o.w = fmaxf(acc.w * dc + sb[jb + 3], 0.f);
    reinterpret_cast<float4*>(h)[(size_t)c * 16 + l] = o;
}

// wab[k][0:64] = lin1_W[k][:], wab[k][64:128] = lin1_W[64+k][:]
__global__ void repack_wab(const float* __restrict__ l1W, float* __restrict__ wab) {
    int i = blockIdx.x * blockDim.x + threadIdx.x;
    if (i < 64 * 128) {
        int k = i >> 7, nn = i & 127;
        wab[i] = (nn < 64) ? l1W[k * 64 + nn] : l1W[(64 + k) * 64 + (nn - 64)];
    }
}

// per edge: z = relu(A[r]+B[c]+b1); logits = z@L2 + b2; log_softmax(2)
__global__ void edge_mlp(const int* __restrict__ row, const int* __restrict__ col,
                         const float* __restrict__ ab, const float* __restrict__ l1b,
                         const float* __restrict__ l2w, const float* __restrict__ l2b,
                         float* __restrict__ out, int E) {
    __shared__ float s1b[64], s2w[128], s2b[2];
    int tid = threadIdx.x;
    if (tid < 64)        s1b[tid]       = l1b[tid];
    else if (tid < 192)  s2w[tid - 64]  = l2w[tid - 64];
    else if (tid < 194)  s2b[tid - 192] = l2b[tid - 192];
    __syncthreads();
    int gid = blockIdx.x * 256 + tid;
    int e = gid >> 4;
    if (e >= E) return;
    int l = gid & 15;
    int r = row[e], c = col[e];
    float4 a = *reinterpret_cast<const float4*>(&ab[(size_t)r * 128 + l * 4]);
    float4 b = *reinterpret_cast<const float4*>(&ab[(size_t)c * 128 + 64 + l * 4]);
    int j = l * 4;
    float s0 = 0.f, s1 = 0.f, z;
    z = fmaxf(a.x + b.x + s1b[j + 0], 0.f); s0 += z * s2w[(j + 0) * 2]; s1 += z * s2w[(j + 0) * 2 + 1];
    z = fmaxf(a.y + b.y + s1b[j + 1], 0.f); s0 += z * s2w[(j + 1) * 2]; s1 += z * s2w[(j + 1) * 2 + 1];
    z = fmaxf(a.z + b.z + s1b[j + 2], 0.f); s0 += z * s2w[(j + 2) * 2]; s1 += z * s2w[(j + 2) * 2 + 1];
    z = fmaxf(a.w + b.w + s1b[j + 3], 0.f); s0 += z * s2w[(j + 3) * 2]; s1 += z * s2w[(j + 3) * 2 + 1];
#pragma unroll
    for (int off = 8; off > 0; off >>= 1) {
        s0 += __shfl_down_sync(0xFFFFFFFFu, s0, off, 16);
        s1 += __shfl_down_sync(0xFFFFFFFFu, s1, off, 16);
    }
    if (l == 0) {
        s0 += s2b[0]; s1 += s2b[1];
        float m = fmaxf(s0, s1);
        float lse = m + logf(expf(s0 - m) + expf(s1 - m));
        float2 o = make_float2(s0 - lse, s1 - lse);
        *reinterpret_cast<float2*>(&out[2 * (size_t)e]) = o;
    }
}

extern "C" void kernel_launch(void* const* d_in, const int* in_sizes, int n_in,
                              void* d_out, int out_size) {
    const float* x   = (const float*)d_in[0];
    const int*   ei  = (const int*)d_in[1];
    const float* W1  = (const float*)d_in[2];
    const float* b1  = (const float*)d_in[3];
    const float* W2  = (const float*)d_in[4];
    const float* b2  = (const float*)d_in[5];
    const float* l1W = (const float*)d_in[6];
    const float* l1b = (const float*)d_in[7];
    const float* l2W = (const float*)d_in[8];
    const float* l2b = (const float*)d_in[9];
    float* out = (float*)d_out;

    int n = in_sizes[0] / FIN;
    int E = in_sizes[1] / 2;
    const int* row = ei;
    const int* col = ei + E;

    int *cnt, *off, *cur, *esrc, *bsum;
    float *dinv, *hl, *h, *ab, *wab;
    cudaGetSymbolAddress((void**)&cnt,  g_cnt);
    cudaGetSymbolAddress((void**)&off,  g_off);
    cudaGetSymbolAddress((void**)&cur,  g_cur);
    cudaGetSymbolAddress((void**)&esrc, g_esrc);
    cudaGetSymbolAddress((void**)&bsum, g_bsum);
    cudaGetSymbolAddress((void**)&dinv, g_dinv);
    cudaGetSymbolAddress((void**)&hl,   g_hl);
    cudaGetSymbolAddress((void**)&h,    g_h);
    cudaGetSymbolAddress((void**)&ab,   g_ab);
    cudaGetSymbolAddress((void**)&wab,  g_wab);

    const int T = 256;
    int NB = (n + 255) / 256;

    // CSC build (incoming edges per node) + dinv
    zero_cnt<<<NB, T>>>(cnt, n);
    count_in<<<(E + T - 1) / T, T>>>(col, cnt, E);
    make_dinv<<<NB, T>>>(cnt, dinv, n);
    scan1<<<NB, T>>>(cnt, off, bsum, n);
    scan2<<<1, 512>>>(bsum, NB);
    scan3<<<NB, T>>>(off, bsum, cur, n, E);
    fill_csr<<<(E + T - 1) / T, T>>>(row, col, cur, esrc, E);

    // GCN layer 1: hls = (x@W1)*dinv ; h = relu(dinv*(sum+self) + b1)
    gemm_tiled<128, 64><<<(n + 63) / 64, 256>>>(x, W1, dinv, hl, n);
    gather_agg<<<(n * 16 + T - 1) / T, T>>>(off, esrc, hl, dinv, b1, h, n);

    // GCN layer 2
    gemm_tiled<64, 64><<<(n + 63) / 64, 256>>>(h, W2, dinv, hl, n);
    gather_agg<<<(n * 16 + T - 1) / T, T>>>(off, esrc, hl, dinv, b2, h, n);

    // Edge MLP
    repack_wab<<<(64 * 128 + T - 1) / T, T>>>(l1W, wab);
    gemm_tiled<64, 128><<<(n + 31) / 32, 256>>>(h, wab, (const float*)nullptr, ab, n);
    edge_mlp<<<(E * 16 + T - 1) / T, T>>>(row, col, ab, l1b, l2W, l2b, out, E);
}